// round 12
// baseline (speedup 1.0000x reference)
#include <cuda_runtime.h>
#include <cuda_bf16.h>
#include <cstdint>

#define B_    4
#define KL    128
#define XL    4096
#define DIM   256
#define H_    8
#define HD    32
#define PB    8
#define NDIS  66
#define TDIM  768           // 3*DIM
#define SCALE 0.17677669529663687f
#define NMASK (B_ * H_ * XL * KL)
#define NSPLIT 32           // x-splits for k2/k3

// ---------------- scratch (device globals) ----------------
__device__ float    g_QKVx[B_ * XL * TDIM];
__device__ float    g_QKVk[B_ * KL * TDIM];
__device__ unsigned short g_pack[(size_t)NMASK];       // (b,h,k,x): rd | polar<<7 | mask<<10
__device__ float    g_oriP[NSPLIT * B_ * H_ * KL * PB];
__device__ int      g_mo[B_ * H_ * KL];
__device__ float    g_part[(size_t)B_ * H_ * NSPLIT * KL * 33];  // (l, acc[32])
__device__ unsigned g_flags;
// pre-split bf16 hi/lo operand storage (u32 = packed bf16x2 along K)
__device__ uint32_t g_xhi[B_ * XL * DIM / 2],  g_xlo[B_ * XL * DIM / 2];
__device__ uint32_t g_khi[B_ * KL * DIM / 2],  g_klo[B_ * KL * DIM / 2];
__device__ uint32_t g_wqh[(DIM / 2) * TDIM],   g_wql[(DIM / 2) * TDIM];
__device__ uint32_t g_wph[(DIM / 2) * DIM],    g_wpl[(DIM / 2) * DIM];
__device__ uint32_t g_pXh[B_ * XL * DIM / 2],  g_pXl[B_ * XL * DIM / 2];
__device__ uint32_t g_pKh[B_ * KL * DIM / 2],  g_pKl[B_ * KL * DIM / 2];

// ---------------- f32x2 packed helpers ----------------
__device__ __forceinline__ uint64_t pk2(float lo, float hi)
{
    uint64_t r;
    asm("mov.b64 %0, {%1, %2};" : "=l"(r) : "f"(lo), "f"(hi));
    return r;
}
__device__ __forceinline__ void upk2(float& lo, float& hi, uint64_t v)
{
    asm("mov.b64 {%0, %1}, %2;" : "=f"(lo), "=f"(hi) : "l"(v));
}
__device__ __forceinline__ void fma2(uint64_t& d, uint64_t a, uint64_t b)
{
    asm("fma.rn.f32x2 %0, %1, %2, %0;" : "+l"(d) : "l"(a), "l"(b));
}

// ---------------- cp.async helpers ----------------
#define CP_ASYNC16(dst_u32, src_ptr) \
    asm volatile("cp.async.ca.shared.global [%0], [%1], 16;" :: "r"(dst_u32), "l"(src_ptr))
#define CP_COMMIT() asm volatile("cp.async.commit_group;")
#define CP_WAIT1()  asm volatile("cp.async.wait_group 1;")
#define CP_WAIT0()  asm volatile("cp.async.wait_group 0;")

// ---------------- bf16 split helper ----------------
__device__ __forceinline__ uint32_t split_pack(float x0, float x1, uint32_t& lo_pack)
{
    __nv_bfloat16 h0 = __float2bfloat16(x0);
    __nv_bfloat16 h1 = __float2bfloat16(x1);
    float l0 = x0 - __bfloat162float(h0);
    float l1 = x1 - __bfloat162float(h1);
    __nv_bfloat162 hp = __halves2bfloat162(h0, h1);
    __nv_bfloat162 lp = __halves2bfloat162(__float2bfloat16(l0), __float2bfloat16(l1));
    lo_pack = *(uint32_t*)&lp;
    return *(uint32_t*)&hp;
}

// ---------------- mask dtype probe ----------------
__global__ void det_reset() { if (threadIdx.x == 0) g_flags = 0u; }

__global__ void det_scan(const unsigned* __restrict__ w)
{
    int i = blockIdx.x * blockDim.x + threadIdx.x;
    unsigned v = w[i];
    unsigned f = 0;
    if (v == 0x3F800000u) f |= 1u;
    else if (v != 0u && v != 1u) f |= 2u;
    for (int o = 16; o > 0; o >>= 1) f |= __shfl_xor_sync(0xffffffffu, f, o);
    if ((threadIdx.x & 31) == 0 && f) atomicOr(&g_flags, f);
}

// ---------------- presplit kernels ----------------
__global__ void presplitA(const float* __restrict__ A,
                          uint32_t* __restrict__ hi, uint32_t* __restrict__ lo, int n)
{
    int i = blockIdx.x * blockDim.x + threadIdx.x;
    if (i >= n) return;
    float2 v = *(const float2*)&A[2 * i];
    uint32_t l, h = split_pack(v.x, v.y, l);
    hi[i] = h; lo[i] = l;
}

__global__ void presplitB(const float* __restrict__ Bm,
                          uint32_t* __restrict__ hi, uint32_t* __restrict__ lo, int N, int n)
{
    int i = blockIdx.x * blockDim.x + threadIdx.x;
    if (i >= n) return;
    int p = i / N, c = i - p * N;
    uint32_t l, h = split_pack(Bm[(size_t)(2 * p) * N + c], Bm[(size_t)(2 * p + 1) * N + c], l);
    hi[i] = h; lo[i] = l;
}

// ---------------- pack16 ----------------
__global__ void pack16(const void* __restrict__ mask,
                       const int* __restrict__ rd, const int* __restrict__ polar)
{
    __shared__ unsigned short rp_sh[32][66];
    __shared__ uint8_t m_sh[64][36];
    unsigned flags = g_flags;
    int mode = (flags & 1u) ? 2 : ((flags & 2u) ? 0 : 1);
    int x0 = blockIdx.x * 64, k0 = blockIdx.y * 32, b = blockIdx.z;
    int tx = threadIdx.x, ty = threadIdx.y;

#pragma unroll
    for (int ki = ty; ki < 32; ki += 8) {
        size_t rowb = ((size_t)(b * KL + k0 + ki)) * XL + x0;
#pragma unroll
        for (int xx = tx; xx < 64; xx += 32) {
            int r = rd[rowb + xx];
            int p = polar[rowb + xx];
            rp_sh[ki][xx] = (unsigned short)(r | (p << 7));
        }
    }
    for (int h = 0; h < H_; h++) {
        size_t mb = ((size_t)((b * H_ + h)) * XL + x0) * KL + k0;
#pragma unroll
        for (int xi = ty; xi < 64; xi += 8) {
            uint8_t v;
            if (mode == 1)      v = ((const int*)mask)[mb + (size_t)xi * KL + tx] != 0;
            else if (mode == 2) v = ((const float*)mask)[mb + (size_t)xi * KL + tx] != 0.f;
            else                v = ((const uint8_t*)mask)[mb + (size_t)xi * KL + tx] != 0;
            m_sh[xi][tx] = v;
        }
        __syncthreads();
        size_t ob = ((size_t)((b * H_ + h) * KL + k0)) * XL + x0;
#pragma unroll
        for (int ki = ty; ki < 32; ki += 8)
#pragma unroll
            for (int xx = tx; xx < 64; xx += 32)
                g_pack[ob + (size_t)ki * XL + xx] =
                    (unsigned short)(rp_sh[ki][xx] | ((unsigned short)m_sh[xx][ki] << 10));
        __syncthreads();
    }
}

// ---------------- bf16x3 GEMM, cp.async double-buffered (BK=16) -----------
__device__ __forceinline__ void mma_bf16(float* c, const uint32_t* a, uint32_t b0, uint32_t b1)
{
    asm("mma.sync.aligned.m16n8k16.row.col.f32.bf16.bf16.f32 "
        "{%0,%1,%2,%3}, {%4,%5,%6,%7}, {%8,%9}, {%0,%1,%2,%3};"
        : "+f"(c[0]), "+f"(c[1]), "+f"(c[2]), "+f"(c[3])
        : "r"(a[0]), "r"(a[1]), "r"(a[2]), "r"(a[3]), "r"(b0), "r"(b1));
}

__global__ __launch_bounds__(256, 2) void gemm_pre(
    const uint32_t* __restrict__ Ahi, const uint32_t* __restrict__ Alo,
    const uint32_t* __restrict__ Bhi, const uint32_t* __restrict__ Blo,
    const float* __restrict__ bias, float* __restrict__ C,
    int M, int N, int K)
{
    // per buffer: A 128 rows x 8 pairs (pad 12), B 8 pair-rows x 128 (pad 136)
    __shared__ uint32_t AsH[2][128][12];
    __shared__ uint32_t AsL[2][128][12];
    __shared__ uint32_t BsH[2][8][136];
    __shared__ uint32_t BsL[2][8][136];
    int tid = threadIdx.x;
    int wid = tid >> 5, lane = tid & 31;
    int g = lane >> 2, t = lane & 3;
    int wm = wid & 1, wn = wid >> 1;
    int cCol = blockIdx.x, cRow = blockIdx.y;
    const int KP = K >> 1;
    const int nIter = KP >> 3;   // 8 pairs per iter

    // smem byte offsets for cp.async
    uint32_t sAH = (uint32_t)__cvta_generic_to_shared(&AsH[0][0][0]);
    uint32_t sAL = (uint32_t)__cvta_generic_to_shared(&AsL[0][0][0]);
    uint32_t sBH = (uint32_t)__cvta_generic_to_shared(&BsH[0][0][0]);
    uint32_t sBL = (uint32_t)__cvta_generic_to_shared(&BsL[0][0][0]);
    const uint32_t A_BUF = 128 * 12 * 4;   // bytes per A buffer
    const uint32_t B_BUF = 8 * 136 * 4;

    // per-thread load coordinates
    int ar_ld = tid >> 1, ap4 = (tid & 1) * 4;      // A: 128 rows x 2 chunks
    int bpr = tid >> 5, bc4 = (tid & 31) * 4;       // B: 8 rows x 32 chunks

    const uint32_t* Abase = Ahi + (size_t)(cRow * 128 + ar_ld) * KP + ap4;
    const uint32_t* AbaseL = Alo + (size_t)(cRow * 128 + ar_ld) * KP + ap4;
    const uint32_t* Bbase = Bhi + (size_t)bpr * N + cCol * 128 + bc4;
    const uint32_t* BbaseL = Blo + (size_t)bpr * N + cCol * 128 + bc4;
    uint32_t dA = (uint32_t)(ar_ld * 12 + ap4) * 4;
    uint32_t dB = (uint32_t)(bpr * 136 + bc4) * 4;

    float acc[4][4][4];
#pragma unroll
    for (int i = 0; i < 4; i++)
#pragma unroll
        for (int j = 0; j < 4; j++)
#pragma unroll
            for (int c = 0; c < 4; c++) acc[i][j][c] = 0.f;

    // prologue: load tile 0 into buffer 0
    CP_ASYNC16(sAH + dA, Abase);
    CP_ASYNC16(sAL + dA, AbaseL);
    CP_ASYNC16(sBH + dB, Bbase);
    CP_ASYNC16(sBL + dB, BbaseL);
    CP_COMMIT();

    for (int it = 0; it < nIter; it++) {
        int buf = it & 1;
        if (it + 1 < nIter) {
            int k1 = (it + 1) * 8;
            int nb = buf ^ 1;
            CP_ASYNC16(sAH + nb * A_BUF + dA, Abase + k1);
            CP_ASYNC16(sAL + nb * A_BUF + dA, AbaseL + k1);
            CP_ASYNC16(sBH + nb * B_BUF + dB, Bbase + (size_t)k1 * N);
            CP_ASYNC16(sBL + nb * B_BUF + dB, BbaseL + (size_t)k1 * N);
            CP_COMMIT();
            CP_WAIT1();
        } else {
            CP_WAIT0();
        }
        __syncthreads();

        uint32_t ah[4][4], al[4][4];
#pragma unroll
        for (int mi = 0; mi < 4; mi++) {
            int ar = wm * 64 + mi * 16 + g;
            ah[mi][0] = AsH[buf][ar][t];         al[mi][0] = AsL[buf][ar][t];
            ah[mi][1] = AsH[buf][ar + 8][t];     al[mi][1] = AsL[buf][ar + 8][t];
            ah[mi][2] = AsH[buf][ar][t + 4];     al[mi][2] = AsL[buf][ar][t + 4];
            ah[mi][3] = AsH[buf][ar + 8][t + 4]; al[mi][3] = AsL[buf][ar + 8][t + 4];
        }
#pragma unroll
        for (int ni = 0; ni < 4; ni++) {
            int bc = wn * 32 + ni * 8 + g;
            uint32_t bh0 = BsH[buf][t][bc], bh1 = BsH[buf][t + 4][bc];
            uint32_t bl0 = BsL[buf][t][bc], bl1 = BsL[buf][t + 4][bc];
#pragma unroll
            for (int mi = 0; mi < 4; mi++) {
                mma_bf16(acc[mi][ni], ah[mi], bh0, bh1);
                mma_bf16(acc[mi][ni], al[mi], bh0, bh1);
                mma_bf16(acc[mi][ni], ah[mi], bl0, bl1);
            }
        }
        __syncthreads();
    }

#pragma unroll
    for (int mi = 0; mi < 4; mi++) {
#pragma unroll
        for (int ni = 0; ni < 4; ni++) {
            int r0 = cRow * 128 + wm * 64 + mi * 16 + g;
            int c0 = cCol * 128 + wn * 32 + ni * 8 + 2 * t;
            float b0 = bias ? bias[c0] : 0.f;
            float b1 = bias ? bias[c0 + 1] : 0.f;
            float2 v01 = make_float2(acc[mi][ni][0] + b0, acc[mi][ni][1] + b1);
            float2 v23 = make_float2(acc[mi][ni][2] + b0, acc[mi][ni][3] + b1);
            *(float2*)&C[(size_t)r0 * N + c0] = v01;
            *(float2*)&C[(size_t)(r0 + 8) * N + c0] = v23;
        }
    }
}

// ---------------- K2: orientation bins (f32x2 scores) ----------------
__global__ __launch_bounds__(128) void k2_scores()
{
    int k = threadIdx.x;
    int xc = blockIdx.x, h = blockIdx.y, b = blockIdx.z;
    int bh = b * H_ + h;
    int xbase = xc * (XL / NSPLIT);
    __shared__ float kx_sh[64 * 32];
    __shared__ unsigned pk_sh[128 * 33];

    uint64_t kq2[16];
    {
        const uint64_t* kqp = (const uint64_t*)&g_QKVk[((size_t)(b * KL + k)) * TDIM + h * HD];
#pragma unroll
        for (int i = 0; i < 16; i++) kq2[i] = kqp[i];
    }

    float bins[8];
#pragma unroll
    for (int o = 0; o < 8; o++) bins[o] = 0.f;

    const unsigned* pkg = (const unsigned*)&g_pack[(size_t)bh * KL * XL];

    for (int c = 0; c < 2; c++) {
        int xs = xbase + c * 64;
        __syncthreads();
        for (int g = threadIdx.x; g < 512; g += 128) {
            int row = g >> 3, c4 = g & 7;
            ((float4*)kx_sh)[g] =
                *(const float4*)&g_QKVx[((size_t)(b * XL + xs + row)) * TDIM + DIM + h * HD + c4 * 4];
        }
        for (int g = threadIdx.x; g < 128 * 32; g += 128) {
            int row = g >> 5, col = g & 31;
            pk_sh[row * 33 + col] = pkg[(size_t)row * (XL / 2) + (xs >> 1) + col];
        }
        __syncthreads();
        const unsigned short* prow = (const unsigned short*)&pk_sh[k * 33];
        for (int j0 = 0; j0 < 64; j0 += 4) {
#pragma unroll
            for (int jj = 0; jj < 4; jj++) {
                const ulonglong2* kx2 = (const ulonglong2*)&kx_sh[(j0 + jj) * 32];
                uint64_t sa = 0;
#pragma unroll
                for (int d = 0; d < 8; d++) {
                    ulonglong2 v = kx2[d];
                    fma2(sa, kq2[2 * d], v.x);
                    fma2(sa, kq2[2 * d + 1], v.y);
                }
                float s0, s1;
                upk2(s0, s1, sa);
                float as = fabsf((s0 + s1) * SCALE);
                int pv = (prow[j0 + jj] >> 7) & 7;
#pragma unroll
                for (int o = 0; o < 8; o++) bins[o] += (pv == o) ? as : 0.f;
            }
        }
    }
    float* orow = &g_oriP[((size_t)xc * B_ * H_ * KL + bh * KL + k) * 8];
#pragma unroll
    for (int o = 0; o < 8; o++) orow[o] = bins[o];
}

// ---------------- K2c: reduce slices + argmax ----------------
__global__ void k2_argmax()
{
    int idx = blockIdx.x * blockDim.x + threadIdx.x;
    if (idx >= B_ * H_ * KL) return;
    float s[8];
#pragma unroll
    for (int o = 0; o < 8; o++) s[o] = 0.f;
    for (int xc = 0; xc < NSPLIT; xc++) {
        const float* p = &g_oriP[((size_t)xc * B_ * H_ * KL + idx) * 8];
#pragma unroll
        for (int o = 0; o < 8; o++) s[o] += p[o];
    }
    int best = 0;
    float bv = s[0];
#pragma unroll
    for (int p = 1; p < 8; p++)
        if (s[p] > bv) { bv = s[p]; best = p; }
    g_mo[idx] = best;
}

// ---------------- K3: kernel->x attention (f32x2, no-max softmax) ---------
__global__ __launch_bounds__(128) void k3_kattn(
    const float* __restrict__ dis_embed, const float* __restrict__ polar_emb)
{
    int k = threadIdx.x;
    int xs = blockIdx.x, h = blockIdx.y, b = blockIdx.z;
    int bh = b * H_ + h;
    __shared__ float kx_sh[64 * 32];
    __shared__ float V_sh[64 * 32];
    __shared__ unsigned pk_sh[128 * 33];
    __shared__ float de_sh[NDIS];
    __shared__ float pe_sh[8];
    if (k < NDIS) de_sh[k] = dis_embed[k * H_ + h];
    if (k < 8) pe_sh[k] = polar_emb[k];
    int mo = g_mo[bh * KL + k];

    uint64_t kq2[16];
    {
        const uint64_t* kqp = (const uint64_t*)&g_QKVk[((size_t)(b * KL + k)) * TDIM + h * HD];
#pragma unroll
        for (int i = 0; i < 16; i++) kq2[i] = kqp[i];
    }

    const unsigned* pkg = (const unsigned*)&g_pack[(size_t)bh * KL * XL];

    float l = 0.f;
    uint64_t acc2[16];
#pragma unroll
    for (int d = 0; d < 16; d++) acc2[d] = 0;

    int xbase = xs * (XL / NSPLIT);
    for (int c = 0; c < 2; c++) {
        int x0 = xbase + c * 64;
        __syncthreads();
        for (int g = threadIdx.x; g < 512; g += 128) {
            int row = g >> 3, c4 = g & 7;
            size_t rb = ((size_t)(b * XL + x0 + row)) * TDIM + h * HD + c4 * 4;
            ((float4*)kx_sh)[g] = *(const float4*)&g_QKVx[rb + DIM];
            ((float4*)V_sh)[g]  = *(const float4*)&g_QKVx[rb + 2 * DIM];
        }
        for (int g = threadIdx.x; g < 128 * 32; g += 128) {
            int row = g >> 5, col = g & 31;
            pk_sh[row * 33 + col] = pkg[(size_t)row * (XL / 2) + (x0 >> 1) + col];
        }
        __syncthreads();
        const unsigned short* prow = (const unsigned short*)&pk_sh[k * 33];
        for (int j0 = 0; j0 < 64; j0 += 4) {
#pragma unroll
            for (int jj = 0; jj < 4; jj++) {
                int j = j0 + jj;
                const ulonglong2* kx2 = (const ulonglong2*)&kx_sh[j * 32];
                uint64_t sa = 0;
#pragma unroll
                for (int d = 0; d < 8; d++) {
                    ulonglong2 v = kx2[d];
                    fma2(sa, kq2[2 * d], v.x);
                    fma2(sa, kq2[2 * d + 1], v.y);
                }
                float s0, s1;
                upk2(s0, s1, sa);
                unsigned short p = prow[j];
                float t = (s0 + s1) * SCALE + de_sh[p & 127] + pe_sh[(((p >> 7) & 7) - mo) & 7];
                float w = (p >> 10) ? 0.f : __expf(t);
                l += w;
                uint64_t wpk = pk2(w, w);
                const ulonglong2* vp = (const ulonglong2*)&V_sh[j * 32];
#pragma unroll
                for (int d = 0; d < 8; d++) {
                    ulonglong2 v = vp[d];
                    fma2(acc2[2 * d], wpk, v.x);
                    fma2(acc2[2 * d + 1], wpk, v.y);
                }
            }
        }
    }
    float* pp = &g_part[(((size_t)bh * NSPLIT + xs) * KL + k) * 33];
    pp[0] = l;
#pragma unroll
    for (int d = 0; d < 16; d++) {
        float a0, a1;
        upk2(a0, a1, acc2[d]);
        pp[1 + 2 * d] = a0;
        pp[2 + 2 * d] = a1;
    }
}

// ---------------- K3c: combine x-splits -> preK (bf16 hi/lo out) ----------
__global__ void k3_combine()
{
    int idx = blockIdx.x * blockDim.x + threadIdx.x;
    if (idx >= B_ * H_ * KL * 16) return;
    int d2 = idx & 15;
    int k = (idx >> 4) & (KL - 1);
    int bh = idx >> 11;
    int h = bh % H_, b = bh / H_;
    const float* base = &g_part[((size_t)bh * NSPLIT) * KL * 33 + (size_t)k * 33];
    float L = 0.f, A0 = 0.f, A1 = 0.f;
    const size_t SSTR = (size_t)KL * 33;
#pragma unroll 8
    for (int s = 0; s < NSPLIT; s++) {
        L  += base[s * SSTR];
        A0 += base[s * SSTR + 1 + 2 * d2];
        A1 += base[s * SSTR + 2 + 2 * d2];
    }
    float invL = 1.f / L;
    uint32_t lo, hi = split_pack(A0 * invL, A1 * invL, lo);
    size_t o = ((size_t)b * KL + k) * (DIM / 2) + h * (HD / 2) + d2;
    g_pKh[o] = hi;
    g_pKl[o] = lo;
}

// ---------------- K4: x->kernel attention (f32x2, bf16 hi/lo out) ---------
__global__ __launch_bounds__(128) void k4_xattn(
    const float* __restrict__ dis_embed, const float* __restrict__ polar_emb)
{
    __shared__ float kk_sh[KL * HD];
    __shared__ float kv_sh[KL * HD];
    __shared__ float de_sh[NDIS];
    __shared__ float pe_sh[8];
    __shared__ int   mo_sh[KL];
    int tid = threadIdx.x;
    int xc = blockIdx.x, h = blockIdx.y, b = blockIdx.z;
    int bh = b * H_ + h;

    for (int g = tid; g < KL * HD / 4; g += 128) {
        int row = g >> 3, c4 = g & 7;
        ((float4*)kk_sh)[g] =
            *(const float4*)&g_QKVk[((size_t)(b * KL + row)) * TDIM + DIM + h * HD + c4 * 4];
        ((float4*)kv_sh)[g] =
            *(const float4*)&g_QKVk[((size_t)(b * KL + row)) * TDIM + 2 * DIM + h * HD + c4 * 4];
    }
    if (tid < NDIS) de_sh[tid] = dis_embed[tid * H_ + h];
    if (tid < 8) pe_sh[tid] = polar_emb[tid];
    if (tid < KL) mo_sh[tid] = g_mo[bh * KL + tid];
    __syncthreads();

    int x = xc * 128 + tid;
    uint64_t q2[16];
    {
        const uint64_t* qp = (const uint64_t*)&g_QKVx[((size_t)(b * XL + x)) * TDIM + h * HD];
#pragma unroll
        for (int i = 0; i < 16; i++) q2[i] = qp[i];
    }
    const unsigned short* pk = &g_pack[(size_t)bh * KL * XL + x];

    float l = 0.f;
    uint64_t acc2[16];
#pragma unroll
    for (int d = 0; d < 16; d++) acc2[d] = 0;

    for (int k0 = 0; k0 < KL; k0 += 4) {
#pragma unroll
        for (int ki = 0; ki < 4; ki++) {
            int kidx = k0 + ki;
            const ulonglong2* kkp = (const ulonglong2*)&kk_sh[kidx * HD];
            uint64_t sa = 0;
#pragma unroll
            for (int d = 0; d < 8; d++) {
                ulonglong2 v = kkp[d];
                fma2(sa, q2[2 * d], v.x);
                fma2(sa, q2[2 * d + 1], v.y);
            }
            float s0, s1;
            upk2(s0, s1, sa);
            unsigned short p = pk[(size_t)kidx * XL];
            float t = (s0 + s1) * SCALE + de_sh[p & 127] + pe_sh[(((p >> 7) & 7) - mo_sh[kidx]) & 7];
            float w = (p >> 10) ? 0.f : __expf(t);
            l += w;
            uint64_t wpk = pk2(w, w);
            const ulonglong2* vp = (const ulonglong2*)&kv_sh[kidx * HD];
#pragma unroll
            for (int d = 0; d < 8; d++) {
                ulonglong2 v = vp[d];
                fma2(acc2[2 * d], wpk, v.x);
                fma2(acc2[2 * d + 1], wpk, v.y);
            }
        }
    }
    float invl = 1.f / l;
    size_t ob = ((size_t)(b * XL + x)) * (DIM / 2) + h * (HD / 2);
#pragma unroll
    for (int d2 = 0; d2 < 16; d2++) {
        float a0, a1;
        upk2(a0, a1, acc2[d2]);
        uint32_t lo, hi = split_pack(a0 * invl, a1 * invl, lo);
        g_pXh[ob + d2] = hi;
        g_pXl[ob + d2] = lo;
    }
}

// ---------------- host launcher ----------------
extern "C" void kernel_launch(void* const* d_in, const int* in_sizes, int n_in,
                              void* d_out, int out_size)
{
    const float* x     = (const float*)d_in[0];
    const float* kern  = (const float*)d_in[1];
    const int*   rd    = (const int*)d_in[2];
    const int*   polar = (const int*)d_in[3];
    const void*  mask  = d_in[4];
    const float* Wqkv  = (const float*)d_in[5];
    const float* dis   = (const float*)d_in[6];
    const float* pemb  = (const float*)d_in[7];
    const float* Wproj = (const float*)d_in[8];
    const float* bproj = (const float*)d_in[9];
    float* out = (float*)d_out;

    float* pQKVx; cudaGetSymbolAddress((void**)&pQKVx, g_QKVx);
    float* pQKVk; cudaGetSymbolAddress((void**)&pQKVk, g_QKVk);
    uint32_t *pxh, *pxl, *pkh, *pkl, *pwqh, *pwql, *pwph, *pwpl, *pXh, *pXl, *pKh, *pKl;
    cudaGetSymbolAddress((void**)&pxh, g_xhi);  cudaGetSymbolAddress((void**)&pxl, g_xlo);
    cudaGetSymbolAddress((void**)&pkh, g_khi);  cudaGetSymbolAddress((void**)&pkl, g_klo);
    cudaGetSymbolAddress((void**)&pwqh, g_wqh); cudaGetSymbolAddress((void**)&pwql, g_wql);
    cudaGetSymbolAddress((void**)&pwph, g_wph); cudaGetSymbolAddress((void**)&pwpl, g_wpl);
    cudaGetSymbolAddress((void**)&pXh, g_pXh);  cudaGetSymbolAddress((void**)&pXl, g_pXl);
    cudaGetSymbolAddress((void**)&pKh, g_pKh);  cudaGetSymbolAddress((void**)&pKl, g_pKl);

    // mask dtype probe + packed bias table
    det_reset<<<1, 32>>>();
    det_scan<<<256, 256>>>((const unsigned*)mask);
    pack16<<<dim3(XL / 64, KL / 32, B_), dim3(32, 8)>>>(mask, rd, polar);

    // pre-split GEMM operands
    presplitA<<<(B_ * XL * DIM / 2 + 255) / 256, 256>>>(x, pxh, pxl, B_ * XL * DIM / 2);
    presplitA<<<(B_ * KL * DIM / 2 + 255) / 256, 256>>>(kern, pkh, pkl, B_ * KL * DIM / 2);
    presplitB<<<((DIM / 2) * TDIM + 255) / 256, 256>>>(Wqkv, pwqh, pwql, TDIM, (DIM / 2) * TDIM);
    presplitB<<<((DIM / 2) * DIM + 255) / 256, 256>>>(Wproj, pwph, pwpl, DIM, (DIM / 2) * DIM);

    // QKV projections
    gemm_pre<<<dim3(TDIM / 128, (B_ * XL) / 128), 256>>>(pxh, pxl, pwqh, pwql, nullptr, pQKVx, B_ * XL, TDIM, DIM);
    gemm_pre<<<dim3(TDIM / 128, (B_ * KL) / 128), 256>>>(pkh, pkl, pwqh, pwql, nullptr, pQKVk, B_ * KL, TDIM, DIM);

    // orientation bins + argmax
    k2_scores<<<dim3(NSPLIT, H_, B_), 128>>>();
    k2_argmax<<<(B_ * H_ * KL + 255) / 256, 256>>>();

    // kernel->x attention
    k3_kattn<<<dim3(NSPLIT, H_, B_), 128>>>(dis, pemb);
    k3_combine<<<(B_ * H_ * KL * 16 + 255) / 256, 256>>>();

    // x->kernel attention
    k4_xattn<<<dim3(XL / 128, H_, B_), 128>>>(dis, pemb);

    // output projections
    gemm_pre<<<dim3(DIM / 128, (B_ * XL) / 128), 256>>>(pXh, pXl, pwph, pwpl, bproj, out, B_ * XL, DIM, DIM);
    gemm_pre<<<dim3(DIM / 128, (B_ * KL) / 128), 256>>>(pKh, pKl, pwph, pwpl, bproj, out + (size_t)B_ * XL * DIM, B_ * KL, DIM, DIM);
}